// round 1
// baseline (speedup 1.0000x reference)
#include <cuda_runtime.h>
#include <math.h>

#define BB 8
#define TT 8
#define CIc 64
#define FNC 64
#define HW 1024
#define CG 256
#define NSTATE (BB*FNC*HW)   // 524288

// ---- persistent state (zeroed each launch) ----
__device__ float g_ih[NSTATE];
__device__ float g_ic[NSTATE];
__device__ float g_im[NSTATE];
// ---- scratch ----
__device__ float g_gates[BB*CG*HW];     // conv output (pre-GN)
__device__ float g_mean[BB*8];
__device__ float g_rstd[BB*8];
__device__ float g_oh[NSTATE];          // pre-SAM hidden
__device__ float g_qkvh[BB*192*HW];
__device__ float g_kvm[BB*128*HW];
__device__ float g_Sh[BB*HW*HW];        // 32MB scores (h)
__device__ float g_Sm[BB*HW*HW];        // 32MB scores (m)
__device__ float g_rmaxh[BB*HW], g_rinvh[BB*HW];
__device__ float g_rmaxm[BB*HW], g_rinvm[BB*HW];
__device__ float g_Zcat[BB*128*HW];
__device__ float g_Z[NSTATE];
__device__ float g_g2[BB*192*HW];

__device__ __forceinline__ float sigm(float x){ return 1.f/(1.f+__expf(-x)); }

__global__ void zero_states(){
  int i = blockIdx.x*256 + threadIdx.x;
  if (i < NSTATE){ g_ih[i]=0.f; g_ic[i]=0.f; g_im[i]=0.f; }
}

// ------------------- 3x3 conv: [B,128,32,32] -> [B,256,32,32] -------------------
// grid: B*32 (co tiles of 8), block 256. Each thread: 4 pixels x 8 co.
__global__ __launch_bounds__(256) void conv3x3(const float* __restrict__ xin,
                                               const float* __restrict__ w,
                                               const float* __restrict__ bias, int t)
{
  int b   = blockIdx.x >> 5;
  int co0 = (blockIdx.x & 31) * 8;
  __shared__ float si[8][34][34];
  __shared__ float swt[8][8][9];
  int tid = threadIdx.x;
  int ty = tid >> 5, tx = tid & 31;
  float acc[8][4];
  #pragma unroll
  for (int o=0;o<8;o++){ acc[o][0]=0.f; acc[o][1]=0.f; acc[o][2]=0.f; acc[o][3]=0.f; }

  for (int chunk=0; chunk<16; chunk++){
    __syncthreads();
    const float* src = (chunk<8) ? (xin + ((size_t)(b*TT + t)*CIc + chunk*8)*HW)
                                 : (g_ih + ((size_t)b*FNC + (chunk-8)*8)*HW);
    for (int idx=tid; idx<8*34*34; idx+=256){
      int ci = idx/1156; int rem = idx - ci*1156;
      int yy = rem/34;   int xx = rem - yy*34;
      int gy = yy-1, gx = xx-1;
      float v = 0.f;
      if ((unsigned)gy < 32u && (unsigned)gx < 32u) v = src[ci*HW + (gy<<5) + gx];
      si[ci][yy][xx] = v;
    }
    int ciG = chunk*8;
    for (int idx=tid; idx<8*8*9; idx+=256){
      int o = idx/72; int rem = idx - o*72; int ci = rem/9; int k = rem - ci*9;
      swt[o][ci][k] = w[((size_t)(co0+o)*128 + ciG+ci)*9 + k];
    }
    __syncthreads();
    #pragma unroll
    for (int ci=0; ci<8; ci++){
      #pragma unroll
      for (int k=0;k<9;k++){
        int ky = k/3, kx = k - 3*ky;
        float v0 = si[ci][ty+ky   ][tx+kx];
        float v1 = si[ci][ty+8+ky ][tx+kx];
        float v2 = si[ci][ty+16+ky][tx+kx];
        float v3 = si[ci][ty+24+ky][tx+kx];
        #pragma unroll
        for (int o=0;o<8;o++){
          float wv = swt[o][ci][k];
          acc[o][0] += wv*v0; acc[o][1] += wv*v1;
          acc[o][2] += wv*v2; acc[o][3] += wv*v3;
        }
      }
    }
  }
  #pragma unroll
  for (int o=0;o<8;o++){
    float bv = bias[co0+o];
    float* dst = g_gates + ((size_t)b*CG + co0 + o)*HW;
    dst[tid      ] = acc[o][0]+bv;
    dst[tid + 256] = acc[o][1]+bv;
    dst[tid + 512] = acc[o][2]+bv;
    dst[tid + 768] = acc[o][3]+bv;
  }
}

// ------------------- group norm stats: 64 blocks (b,group) -------------------
__global__ void gn_stats(){
  int bg = blockIdx.x;                // b*8+g
  int b = bg >> 3, g = bg & 7;
  const float* base = g_gates + ((size_t)b*CG + g*32)*HW;
  float s=0.f, s2=0.f;
  for (int i=threadIdx.x; i<32*HW; i+=256){ float v = base[i]; s += v; s2 += v*v; }
  __shared__ float rs[256], rq[256];
  rs[threadIdx.x]=s; rq[threadIdx.x]=s2; __syncthreads();
  for (int off=128; off; off>>=1){
    if (threadIdx.x < off){ rs[threadIdx.x]+=rs[threadIdx.x+off]; rq[threadIdx.x]+=rq[threadIdx.x+off]; }
    __syncthreads();
  }
  if (threadIdx.x==0){
    float m   = rs[0]*(1.f/32768.f);
    float var = rq[0]*(1.f/32768.f) - m*m;
    g_mean[bg] = m;
    g_rstd[bg] = rsqrtf(var + 1e-5f);
  }
}

__device__ __forceinline__ float gnormv(int b, int ch, int p,
                                        const float* __restrict__ gg,
                                        const float* __restrict__ gb){
  float v = g_gates[((size_t)b*CG + ch)*HW + p];
  int grp = ch >> 5;
  return (v - g_mean[b*8+grp]) * g_rstd[b*8+grp] * gg[ch] + gb[ch];
}

// ------------------- GN apply + LSTM gating -------------------
__global__ void gn_lstm(const float* __restrict__ gg, const float* __restrict__ gb){
  int idx = blockIdx.x*256 + threadIdx.x;   // over NSTATE
  int b = idx >> 16; int c = (idx >> 10) & 63; int p = idx & 1023;
  float vi = gnormv(b, c      , p, gg, gb);
  float vf = gnormv(b, c + 64 , p, gg, gb);
  float vc = gnormv(b, c + 128, p, gg, gb);
  float vo = gnormv(b, c + 192, p, gg, gb);
  float oc = g_ic[idx]*sigm(vf) + sigm(vi)*tanhf(vc);
  float oh = sigm(vo)*tanhf(oc);
  g_ic[idx] = oc;
  g_oh[idx] = oh;
}

// ------------------- generic 1x1 conv (optionally concat 2 inputs) -------------------
// grid (B, Cout/16, 4), block 256
__global__ __launch_bounds__(256) void lin1x1(const float* __restrict__ x1, int C1,
                                              const float* __restrict__ x2, int C2,
                                              const float* __restrict__ w,
                                              const float* __restrict__ bias,
                                              float* __restrict__ y, int Cout)
{
  int b = blockIdx.x; int o0 = blockIdx.y*16; int p = blockIdx.z*256 + threadIdx.x;
  int Cin = C1 + C2;
  __shared__ float sw[16*128];
  for (int idx=threadIdx.x; idx<16*Cin; idx+=256){
    int o = idx/Cin, c = idx - o*Cin;
    sw[idx] = w[(size_t)(o0+o)*Cin + c];
  }
  __syncthreads();
  float acc[16];
  #pragma unroll
  for (int o=0;o<16;o++) acc[o] = bias[o0+o];
  const float* xb = x1 + (size_t)b*C1*HW + p;
  for (int c=0;c<C1;c++){
    float xv = xb[(size_t)c*HW];
    #pragma unroll
    for (int o=0;o<16;o++) acc[o] += sw[o*Cin + c]*xv;
  }
  if (C2 > 0){
    const float* xb2 = x2 + (size_t)b*C2*HW + p;
    for (int c=0;c<C2;c++){
      float xv = xb2[(size_t)c*HW];
      #pragma unroll
      for (int o=0;o<16;o++) acc[o] += sw[o*Cin + C1 + c]*xv;
    }
  }
  #pragma unroll
  for (int o=0;o<16;o++) y[((size_t)b*Cout + o0+o)*HW + p] = acc[o];
}

// ------------------- attention scores: S[n,m] = sum_c Q[c,n] K[c,m] -------------------
// grid (B, 64 n-tiles of 16, 4 m-tiles of 256), block 256
__global__ __launch_bounds__(256) void scores(const float* __restrict__ q, int qcs,
                                              const float* __restrict__ k, int kcs,
                                              float* __restrict__ S)
{
  int b = blockIdx.x; int n0 = blockIdx.y*16; int m = blockIdx.z*256 + threadIdx.x;
  __shared__ float sQ[64][16];
  for (int idx=threadIdx.x; idx<1024; idx+=256){
    int c = idx >> 4, j = idx & 15;
    sQ[c][j] = q[((size_t)b*qcs + c)*HW + n0 + j];
  }
  __syncthreads();
  float acc[16];
  #pragma unroll
  for (int j=0;j<16;j++) acc[j]=0.f;
  const float* kb = k + (size_t)b*kcs*HW + m;
  #pragma unroll 4
  for (int c=0;c<64;c++){
    float kv = kb[(size_t)c*HW];
    #pragma unroll
    for (int j=0;j<16;j++) acc[j] += sQ[c][j]*kv;
  }
  float* so = S + ((size_t)b*HW + n0)*HW + m;
  #pragma unroll
  for (int j=0;j<16;j++) so[(size_t)j*HW] = acc[j];
}

// ------------------- per-row max / 1/sumexp -------------------
__global__ void rowstats(const float* __restrict__ S, float* __restrict__ rmax,
                         float* __restrict__ rinv){
  int row = blockIdx.x*8 + (threadIdx.x >> 5);
  int lane = threadIdx.x & 31;
  const float* r = S + (size_t)row*HW;
  float mx = -1e30f;
  for (int m=lane; m<HW; m+=32) mx = fmaxf(mx, r[m]);
  #pragma unroll
  for (int off=16; off; off>>=1) mx = fmaxf(mx, __shfl_xor_sync(0xffffffffu, mx, off));
  float s = 0.f;
  for (int m=lane; m<HW; m+=32) s += __expf(r[m]-mx);
  #pragma unroll
  for (int off=16; off; off>>=1) s += __shfl_xor_sync(0xffffffffu, s, off);
  if (lane==0){ rmax[row]=mx; rinv[row]=1.f/s; }
}

// ------------------- Z[c,m] = sum_n V[c,n] * softmax(S)[n,m] -------------------
// grid (B, 32 m-tiles of 32), block 256: tid -> (c=tid&63, mq=tid>>6), 8 m's each
__global__ __launch_bounds__(256) void av(const float* __restrict__ S,
                                          const float* __restrict__ rmax,
                                          const float* __restrict__ rinv,
                                          const float* __restrict__ V, int vcs,
                                          float* __restrict__ Z, int zcs, int zoff)
{
  int b = blockIdx.x; int m0 = blockIdx.y*32;
  int tid = threadIdx.x;
  int c = tid & 63, mq = tid >> 6;
  __shared__ float sP[64][32];
  __shared__ float sV[64][65];
  float acc[8];
  #pragma unroll
  for (int j=0;j<8;j++) acc[j]=0.f;
  for (int nb=0; nb<HW; nb+=64){
    __syncthreads();
    for (int idx=tid; idx<64*32; idx+=256){
      int n = idx >> 5, mm = idx & 31;
      int rowg = b*HW + nb + n;
      float sv = S[(size_t)rowg*HW + m0 + mm];
      sP[n][mm] = __expf(sv - rmax[rowg]) * rinv[rowg];
    }
    for (int idx=tid; idx<64*64; idx+=256){
      int cc = idx >> 6, n = idx & 63;
      sV[n][cc] = V[((size_t)b*vcs + cc)*HW + nb + n];
    }
    __syncthreads();
    #pragma unroll 4
    for (int n=0;n<64;n++){
      float v = sV[n][c];
      #pragma unroll
      for (int j=0;j<8;j++) acc[j] += v * sP[n][mq + 4*j];
    }
  }
  #pragma unroll
  for (int j=0;j<8;j++)
    Z[((size_t)b*zcs + zoff + c)*HW + m0 + mq + 4*j] = acc[j];
}

// ------------------- final gating: om, oh2, state update, output write -------------------
__global__ void final_k(float* __restrict__ out, int t, int ws){
  int idx = blockIdx.x*256 + threadIdx.x;
  int b = idx >> 16; int c = (idx >> 10) & 63; int p = idx & 1023;
  const float* g2 = g_g2 + (size_t)b*192*HW + p;
  float vo = g2[(size_t)c*HW];
  float vg = g2[(size_t)(64+c)*HW];
  float vi = g2[(size_t)(128+c)*HW];
  float si = sigm(vi);
  float om  = tanhf(vg)*si + (1.f-si)*g_im[idx];
  float oh2 = sigm(vo)*om;
  g_im[idx] = om;
  g_ih[idx] = oh2;
  out[(((size_t)b*TT + t)*FNC + c)*HW + p] = oh2;
  if (ws){
    float* st = out + (size_t)BB*TT*FNC*HW;
    st[idx]            = oh2;        // ohT
    st[NSTATE + idx]   = g_ic[idx];  // ocT
    st[2*NSTATE + idx] = om;         // imT (om)
  }
}

extern "C" void kernel_launch(void* const* d_in, const int* in_sizes, int n_in,
                              void* d_out, int out_size)
{
  const float* inputs = (const float*)d_in[0];
  const float* conv_w = (const float*)d_in[1];
  const float* conv_b = (const float*)d_in[2];
  const float* gn_g   = (const float*)d_in[3];
  const float* gn_b   = (const float*)d_in[4];
  const float* h_w    = (const float*)d_in[5];
  const float* h_b    = (const float*)d_in[6];
  const float* m_w    = (const float*)d_in[7];
  const float* m_b    = (const float*)d_in[8];
  const float* z1_w   = (const float*)d_in[9];
  const float* z1_b   = (const float*)d_in[10];
  const float* z2_w   = (const float*)d_in[11];
  const float* z2_b   = (const float*)d_in[12];
  float* out = (float*)d_out;

  float *pOh, *pIm, *pQkvh, *pKvm, *pSh, *pSm, *pRmaxh, *pRinvh, *pRmaxm, *pRinvm, *pZcat, *pZ, *pG2;
  cudaGetSymbolAddress((void**)&pOh,    g_oh);
  cudaGetSymbolAddress((void**)&pIm,    g_im);
  cudaGetSymbolAddress((void**)&pQkvh,  g_qkvh);
  cudaGetSymbolAddress((void**)&pKvm,   g_kvm);
  cudaGetSymbolAddress((void**)&pSh,    g_Sh);
  cudaGetSymbolAddress((void**)&pSm,    g_Sm);
  cudaGetSymbolAddress((void**)&pRmaxh, g_rmaxh);
  cudaGetSymbolAddress((void**)&pRinvh, g_rinvh);
  cudaGetSymbolAddress((void**)&pRmaxm, g_rmaxm);
  cudaGetSymbolAddress((void**)&pRinvm, g_rinvm);
  cudaGetSymbolAddress((void**)&pZcat,  g_Zcat);
  cudaGetSymbolAddress((void**)&pZ,     g_Z);
  cudaGetSymbolAddress((void**)&pG2,    g_g2);

  zero_states<<<2048,256>>>();
  int write_states = (out_size >= (int)(BB*TT*FNC*HW + 3*NSTATE)) ? 1 : 0;

  for (int t=0; t<TT; t++){
    conv3x3<<<256,256>>>(inputs, conv_w, conv_b, t);
    gn_stats<<<64,256>>>();
    gn_lstm<<<NSTATE/256,256>>>(gn_g, gn_b);
    // h_qkv from pre-SAM oh; m_kv from previous im
    lin1x1<<<dim3(8,12,4),256>>>(pOh, 64, nullptr, 0, h_w, h_b, pQkvh, 192);
    lin1x1<<<dim3(8, 8,4),256>>>(pIm, 64, nullptr, 0, m_w, m_b, pKvm, 128);
    // scores: Q = qkvh[0:64]; Kh = qkvh[64:128]; Km = kvm[0:64]
    scores<<<dim3(8,64,4),256>>>(pQkvh, 192, pQkvh + (size_t)64*HW, 192, pSh);
    scores<<<dim3(8,64,4),256>>>(pQkvh, 192, pKvm,                  128, pSm);
    rowstats<<<1024,256>>>(pSh, pRmaxh, pRinvh);
    rowstats<<<1024,256>>>(pSm, pRmaxm, pRinvm);
    // Zh = Vh * P_h (Vh = qkvh[128:192]); Zm = Vm * P_m (Vm = kvm[64:128])
    av<<<dim3(8,32),256>>>(pSh, pRmaxh, pRinvh, pQkvh + (size_t)128*HW, 192, pZcat, 128, 0);
    av<<<dim3(8,32),256>>>(pSm, pRmaxm, pRinvm, pKvm  + (size_t)64*HW,  128, pZcat, 128, 64);
    lin1x1<<<dim3(8, 4,4),256>>>(pZcat, 128, nullptr, 0, z1_w, z1_b, pZ, 64);
    lin1x1<<<dim3(8,12,4),256>>>(pZ, 64, pOh, 64, z2_w, z2_b, pG2, 192);
    final_k<<<NSTATE/256,256>>>(out, t, (t==TT-1) ? write_states : 0);
  }
}